// round 1
// baseline (speedup 1.0000x reference)
#include <cuda_runtime.h>
#include <math.h>

#define B   128
#define L   500
#define H   512
#define LD  256
#define UD  128
#define V   33
#define H3  1536
#define NCTA 128
#define NT   512

// ---------------- device scratch (static: no allocations allowed) ------------
__device__ __align__(16) float g_tbl[H3 * V];      // gi table: [3H][V] incl b_ih
__device__ __align__(16) float g_h[2][H * B];      // hidden state, transposed [j][b], ping-pong
__device__ __align__(16) float g_ctxT[H * B];      // attention context, [j][b]
__device__ __align__(16) float g_ccT[H * B];       // concat-proj output, [j][b]
__device__ __align__(16) float g_memWT[UD * H];    // mem_W transposed: [d][j]
__device__ __align__(16) float g_outWT[H * 64];    // out_W transposed+padded: [j][64]
__device__ int g_tok[B];
__device__ unsigned g_cnt;                          // barrier arrive counter (self-resetting)
__device__ unsigned g_gen;                          // barrier generation (monotonic)

// ---------------- software grid barrier (all 128 CTAs co-resident) -----------
__device__ __forceinline__ void gbar() {
    __threadfence();
    __syncthreads();
    if (threadIdx.x == 0) {
        unsigned target = *(volatile unsigned*)&g_gen + 1u;
        unsigned prev = atomicAdd(&g_cnt, 1u);
        if (prev == NCTA - 1) {
            atomicExch(&g_cnt, 0u);
            __threadfence();
            atomicAdd(&g_gen, 1u);
        } else {
            while ((int)(*(volatile unsigned*)&g_gen - target) < 0) {}
        }
    }
    __syncthreads();
    __threadfence();
}

__device__ __forceinline__ float sigf(float x) { return 1.f / (1.f + expf(-x)); }

// ---------------- prep kernels ----------------------------------------------
// gi table: tbl[jg][v] = dot(W_ih[jg,:], embed[v,:]) + b_ih[jg]
__global__ void prep_tbl(const float* __restrict__ embed,
                         const float* __restrict__ W_ih,
                         const float* __restrict__ b_ih) {
    int jg = blockIdx.x;
    int v = threadIdx.x;
    if (v >= V) return;
    const float* wr = W_ih + (size_t)jg * H;
    const float* er = embed + (size_t)v * H;
    float acc = b_ih[jg];
#pragma unroll 4
    for (int k = 0; k < H; ++k) acc += er[k] * wr[k];
    g_tbl[jg * V + v] = acc;
}

// h0[j][b] = dot(hid_W[j,:], latent[b,:]) + hid_b[j]
__global__ void prep_h0(const float* __restrict__ latent,
                        const float* __restrict__ hid_W,
                        const float* __restrict__ hid_b) {
    int j = blockIdx.x;
    int b = threadIdx.x;
    const float* wr = hid_W + (size_t)j * LD;
    const float* lt = latent + (size_t)b * LD;
    float acc = hid_b[j];
#pragma unroll 4
    for (int k = 0; k < LD; ++k) acc += lt[k] * wr[k];
    g_h[0][j * B + b] = acc;
}

// transposes + token init
__global__ void prep_misc(const float* __restrict__ mem_W,
                          const float* __restrict__ out_W) {
    int total = H * UD + H * 64 + B;
    for (int idx = blockIdx.x * blockDim.x + threadIdx.x; idx < total;
         idx += gridDim.x * blockDim.x) {
        if (idx < H * UD) {                       // memWT[d][j] = mem_W[j][d]
            int j = idx >> 7, d = idx & 127;
            g_memWT[d * H + j] = mem_W[idx];
        } else if (idx < H * UD + H * 64) {       // outWT[j][v] (pad v>=33 with 0)
            int i = idx - H * UD;
            int j = i >> 6, v = i & 63;
            g_outWT[i] = (v < V) ? out_W[v * H + j] : 0.f;
        } else {
            g_tok[idx - H * UD - H * 64] = 0;     // SOS = 0
        }
    }
}

// ---------------- main persistent decoder -----------------------------------
__global__ void __launch_bounds__(NT, 1)
decoder_kernel(const float* __restrict__ u,        // [B,L,UD]
               const float* __restrict__ W_hh,     // [3H,H]
               const float* __restrict__ b_hh,     // [3H]
               const float* __restrict__ mem_W,    // [H,UD]
               const float* __restrict__ mem_b,    // [H]
               const float* __restrict__ cat_W,    // [H,2H]
               const float* __restrict__ cat_b,    // [H]
               const float* __restrict__ out_b,    // [V]
               float* __restrict__ out)            // [B,V,L]
{
    __shared__ __align__(16) float SM[6144];      // 24 KB, aliased per phase
    const int tid = threadIdx.x;
    const int cta = blockIdx.x;

    for (int t = 0; t < L; ++t) {
        const float* hin = g_h[t & 1];
        float* hout = g_h[(t + 1) & 1];

        // ================= P1: GRU  (CTA owns 4 output j's, all b) ==========
        {
            const int jc = cta * 4;
            const int bq = tid & 31;              // 4 b's per thread
            const int jl = (tid >> 5) & 3;
            const int kg = tid >> 7;              // k-range split by 4
            // stage 12 W_hh rows (r,z,n gates x 4 j) into SMEM
            for (int i = tid; i < 12 * 512; i += NT) {
                int r = i >> 9, k = i & 511;
                int row = jc + (r & 3) + (r >> 2) * H;
                SM[i] = W_hh[row * H + k];
            }
            __syncthreads();
            float4 ar = {0, 0, 0, 0}, az = ar, an = ar;
            const int k0 = kg * 128;
            const float* hp = hin + k0 * B + bq * 4;
            const float* wr = SM + jl * 512 + k0;
            const float* wz = SM + (4 + jl) * 512 + k0;
            const float* wn = SM + (8 + jl) * 512 + k0;
            for (int k = 0; k < 128; k += 4) {
                float4 w_r = *(const float4*)(wr + k);
                float4 w_z = *(const float4*)(wz + k);
                float4 w_n = *(const float4*)(wn + k);
#pragma unroll
                for (int kk = 0; kk < 4; ++kk) {
                    float4 hv = *(const float4*)(hp + (k + kk) * B);
                    float a = ((const float*)&w_r)[kk];
                    float bz = ((const float*)&w_z)[kk];
                    float c = ((const float*)&w_n)[kk];
                    ar.x += a * hv.x;  ar.y += a * hv.y;  ar.z += a * hv.z;  ar.w += a * hv.w;
                    az.x += bz * hv.x; az.y += bz * hv.y; az.z += bz * hv.z; az.w += bz * hv.w;
                    an.x += c * hv.x;  an.y += c * hv.y;  an.z += c * hv.z;  an.w += c * hv.w;
                }
            }
            __syncthreads();                      // weights dead; reuse SMEM
            float4* psA = (float4*)SM;            // [512] each
            float4* psB = psA + 512;
            float4* psC = psB + 512;
            psA[tid] = ar; psB[tid] = az; psC[tid] = an;
            __syncthreads();
            if (tid < 128) {                      // kg==0 threads: (bq, jl)
                float4 R, Zk, N;
                R.x = psA[tid].x + psA[tid+128].x + psA[tid+256].x + psA[tid+384].x;
                R.y = psA[tid].y + psA[tid+128].y + psA[tid+256].y + psA[tid+384].y;
                R.z = psA[tid].z + psA[tid+128].z + psA[tid+256].z + psA[tid+384].z;
                R.w = psA[tid].w + psA[tid+128].w + psA[tid+256].w + psA[tid+384].w;
                Zk.x = psB[tid].x + psB[tid+128].x + psB[tid+256].x + psB[tid+384].x;
                Zk.y = psB[tid].y + psB[tid+128].y + psB[tid+256].y + psB[tid+384].y;
                Zk.z = psB[tid].z + psB[tid+128].z + psB[tid+256].z + psB[tid+384].z;
                Zk.w = psB[tid].w + psB[tid+128].w + psB[tid+256].w + psB[tid+384].w;
                N.x = psC[tid].x + psC[tid+128].x + psC[tid+256].x + psC[tid+384].x;
                N.y = psC[tid].y + psC[tid+128].y + psC[tid+256].y + psC[tid+384].y;
                N.z = psC[tid].z + psC[tid+128].z + psC[tid+256].z + psC[tid+384].z;
                N.w = psC[tid].w + psC[tid+128].w + psC[tid+256].w + psC[tid+384].w;
                const float* Rf = (const float*)&R;
                const float* Zf = (const float*)&Zk;
                const float* Nf = (const float*)&N;
                int j = jc + jl;
                float bhr = b_hh[j], bhz = b_hh[H + j], bhn = b_hh[2 * H + j];
#pragma unroll
                for (int c = 0; c < 4; ++c) {
                    int b = bq * 4 + c;
                    int tk = g_tok[b];
                    float gr = g_tbl[j * V + tk];
                    float gz = g_tbl[(H + j) * V + tk];
                    float gn = g_tbl[(2 * H + j) * V + tk];
                    float hv = hin[j * B + b];
                    float r = sigf(gr + Rf[c] + bhr);
                    float z = sigf(gz + Zf[c] + bhz);
                    float n = tanhf(gn + r * (Nf[c] + bhn));
                    hout[j * B + b] = (1.f - z) * n + z * hv;
                }
            }
        }
        gbar();

        // ================= P2: attention (CTA = batch element) ==============
        {
            const int b = cta;
            const float* hn = hout;
            // p[d] = sum_j mem_W[j][d] * h_new[j][b]   (partials over 4 j-groups)
            {
                int d = tid & 127, jg = tid >> 7;
                float acc = 0.f;
                const float* mw = mem_W + jg * 128 * UD + d;
                const float* hb = hn + jg * 128 * B + b;
#pragma unroll 4
                for (int j = 0; j < 128; ++j) acc += mw[j * UD] * hb[j * B];
                SM[tid] = acc;
            }
            // sbias = dot(h_new, mem_b)
            {
                float sp = hn[tid * B + b] * mem_b[tid];
#pragma unroll
                for (int o = 16; o > 0; o >>= 1) sp += __shfl_xor_sync(~0u, sp, o);
                if ((tid & 31) == 0) SM[640 + (tid >> 5)] = sp;
            }
            __syncthreads();
            if (tid < 128)
                SM[512 + tid] = SM[tid] + SM[128 + tid] + SM[256 + tid] + SM[384 + tid];
            if (tid == 0) {
                float s = 0.f;
                for (int i = 0; i < 16; ++i) s += SM[640 + i];
                SM[656] = s;
            }
            __syncthreads();
            const float sbias = SM[656];
            const int lane = tid & 31, w = tid >> 5;
            float4 pv = *(const float4*)(SM + 512 + lane * 4);
            const float* ub = u + (size_t)b * (L * UD) + lane * 4;
            // two-stream online softmax + weighted-u accumulation (single u pass)
            float m0 = -1e30f, Z0 = 0.f, m1 = -1e30f, Z1 = 0.f;
            float4 q0 = {0, 0, 0, 0}, q1 = {0, 0, 0, 0};
            for (int l0 = w; l0 < L; l0 += 32) {
                int l1 = l0 + 16;
                bool has1 = (l1 < L);
                float4 u0 = *(const float4*)(ub + l0 * UD);
                float4 u1 = has1 ? *(const float4*)(ub + l1 * UD) : make_float4(0, 0, 0, 0);
                float s0v = u0.x * pv.x + u0.y * pv.y + u0.z * pv.z + u0.w * pv.w;
                float s1v = u1.x * pv.x + u1.y * pv.y + u1.z * pv.z + u1.w * pv.w;
#pragma unroll
                for (int o = 16; o > 0; o >>= 1) {
                    s0v += __shfl_xor_sync(~0u, s0v, o);
                    s1v += __shfl_xor_sync(~0u, s1v, o);
                }
                s0v += sbias; s1v += sbias;
                {
                    float mn = fmaxf(m0, s0v);
                    float sc = expf(m0 - mn), wt = expf(s0v - mn);
                    Z0 = Z0 * sc + wt;
                    q0.x = q0.x * sc + wt * u0.x; q0.y = q0.y * sc + wt * u0.y;
                    q0.z = q0.z * sc + wt * u0.z; q0.w = q0.w * sc + wt * u0.w;
                    m0 = mn;
                }
                if (has1) {
                    float mn = fmaxf(m1, s1v);
                    float sc = expf(m1 - mn), wt = expf(s1v - mn);
                    Z1 = Z1 * sc + wt;
                    q1.x = q1.x * sc + wt * u1.x; q1.y = q1.y * sc + wt * u1.y;
                    q1.z = q1.z * sc + wt * u1.z; q1.w = q1.w * sc + wt * u1.w;
                    m1 = mn;
                }
            }
            {   // merge stream1 into stream0
                float mn = fmaxf(m0, m1);
                float sc0 = expf(m0 - mn), sc1 = expf(m1 - mn);
                Z0 = Z0 * sc0 + Z1 * sc1;
                q0.x = q0.x * sc0 + q1.x * sc1; q0.y = q0.y * sc0 + q1.y * sc1;
                q0.z = q0.z * sc0 + q1.z * sc1; q0.w = q0.w * sc0 + q1.w * sc1;
                m0 = mn;
            }
            __syncthreads();
            *(float4*)(SM + 1024 + w * 128 + lane * 4) = q0;   // per-warp q
            if (lane == 0) { SM[3072 + w] = m0; SM[3088 + w] = Z0; }
            __syncthreads();
            if (tid == 0) {
                float M = SM[3072];
                for (int i = 1; i < 16; ++i) M = fmaxf(M, SM[3072 + i]);
                float Zt = 0.f;
                for (int i = 0; i < 16; ++i) {
                    float e = expf(SM[3072 + i] - M);
                    SM[3104 + i] = e;
                    Zt += e * SM[3088 + i];
                }
                SM[3120] = 1.f / Zt;
            }
            __syncthreads();
            if (tid < 128) {
                float acc = 0.f;
#pragma unroll
                for (int i = 0; i < 16; ++i) acc += SM[3104 + i] * SM[1024 + i * 128 + tid];
                SM[3136 + tid] = acc * SM[3120];               // q_s[d] (softmax-weighted u)
            }
            __syncthreads();
            // ctx[j] = sum_d memWT[d][j] * q_s[d] + mem_b[j]
            {
                int j = tid;
                float acc = 0.f;
#pragma unroll 8
                for (int d = 0; d < UD; ++d) acc += g_memWT[d * H + j] * SM[3136 + d];
                g_ctxT[j * B + b] = acc + mem_b[j];
            }
        }
        gbar();

        // ================= P3: cc = tanh(cat_W @ [h_new;ctx] + cat_b) =======
        {
            const int jc = cta * 4;
            const int bq = tid & 31;
            const int jl = (tid >> 5) & 3;
            const int kg = tid >> 7;              // k in [kg*256, kg*256+256)
            for (int i = tid; i < 4096; i += NT) {
                int jls = i >> 10, k = i & 1023;
                SM[i] = cat_W[(jc + jls) * 1024 + k];
            }
            __syncthreads();
            float4 acc = {0, 0, 0, 0};
            const int k0 = kg * 256;
            const float* xb = (kg < 2) ? (hout + k0 * B) : (g_ctxT + (k0 - 512) * B);
            const float* wp = SM + jl * 1024 + k0;
            for (int i = 0; i < 256; i += 4) {
                float4 w4 = *(const float4*)(wp + i);
#pragma unroll
                for (int kk = 0; kk < 4; ++kk) {
                    float4 xv = *(const float4*)(xb + (i + kk) * B + bq * 4);
                    float wv = ((const float*)&w4)[kk];
                    acc.x += wv * xv.x; acc.y += wv * xv.y;
                    acc.z += wv * xv.z; acc.w += wv * xv.w;
                }
            }
            __syncthreads();
            float4* ps = (float4*)SM;
            ps[tid] = acc;
            __syncthreads();
            if (tid < 128) {
                float4 S;
                S.x = ps[tid].x + ps[tid+128].x + ps[tid+256].x + ps[tid+384].x;
                S.y = ps[tid].y + ps[tid+128].y + ps[tid+256].y + ps[tid+384].y;
                S.z = ps[tid].z + ps[tid+128].z + ps[tid+256].z + ps[tid+384].z;
                S.w = ps[tid].w + ps[tid+128].w + ps[tid+256].w + ps[tid+384].w;
                int j = jc + jl;
                float cb = cat_b[j];
                float4 cc;
                cc.x = tanhf(S.x + cb); cc.y = tanhf(S.y + cb);
                cc.z = tanhf(S.z + cb); cc.w = tanhf(S.w + cb);
                *(float4*)(g_ccT + j * B + bq * 4) = cc;
            }
        }
        gbar();

        // ================= P4: logits + argmax (CTA = batch) ================
        {
            const int b = cta;
            const int v = tid & 63, jg = tid >> 6;
            float acc = 0.f;
            const float* op = g_outWT + jg * 64 * 64 + v;
            const float* cp = g_ccT + jg * 64 * B + b;
#pragma unroll 8
            for (int i = 0; i < 64; ++i) acc += op[i * 64] * cp[i * B];
            SM[jg * 64 + v] = acc;
            __syncthreads();
            if (tid < 64) {
                float s = 0.f;
#pragma unroll
                for (int g = 0; g < 8; ++g) s += SM[g * 64 + tid];
                if (tid < V) {
                    float logit = s + out_b[tid];
                    out[(b * V + tid) * L + t] = logit;
                    SM[512 + tid] = logit;
                }
            }
            __syncthreads();
            if (tid == 0) {   // first-occurrence argmax (matches jnp.argmax)
                float best = SM[512];
                int bi = 0;
                for (int v2 = 1; v2 < V; ++v2) {
                    float lv = SM[512 + v2];
                    if (lv > best) { best = lv; bi = v2; }
                }
                g_tok[b] = bi;
            }
        }
        gbar();
    }
}

// ---------------- launch -----------------------------------------------------
extern "C" void kernel_launch(void* const* d_in, const int* in_sizes, int n_in,
                              void* d_out, int out_size) {
    const float* latent = (const float*)d_in[0];
    const float* u      = (const float*)d_in[1];
    // d_in[2] = target (unused in eval/greedy mode)
    const float* embed  = (const float*)d_in[3];
    const float* hid_W  = (const float*)d_in[4];
    const float* hid_b  = (const float*)d_in[5];
    const float* mem_W  = (const float*)d_in[6];
    const float* mem_b  = (const float*)d_in[7];
    const float* W_ih   = (const float*)d_in[8];
    const float* W_hh   = (const float*)d_in[9];
    const float* b_ih   = (const float*)d_in[10];
    const float* b_hh   = (const float*)d_in[11];
    const float* cat_W  = (const float*)d_in[12];
    const float* cat_b  = (const float*)d_in[13];
    const float* out_W  = (const float*)d_in[14];
    const float* out_b  = (const float*)d_in[15];
    float* out = (float*)d_out;

    prep_tbl<<<H3, 64>>>(embed, W_ih, b_ih);
    prep_h0<<<H, B>>>(latent, hid_W, hid_b);
    prep_misc<<<64, 256>>>(mem_W, out_W);
    decoder_kernel<<<NCTA, NT>>>(u, W_hh, b_hh, mem_W, mem_b,
                                 cat_W, cat_b, out_b, out);
}

// round 2
// speedup vs baseline: 1.7139x; 1.7139x over previous
#include <cuda_runtime.h>
#include <math.h>

#define B   128
#define L   500
#define H   512
#define LD  256
#define UD  128
#define V   33
#define H3  1536
#define NCTA 128
#define NT   512

// dynamic SMEM layout (floats): [0,6144) W_hh rows | [6144,8192) cat_W h-half
// [8192,8704) catM rows | [8704,16896) scratch (stage tiles / reductions)
#define SMEM_FLOATS 16896
#define SMEM_BYTES  (SMEM_FLOATS * 4)

// ---------------- device scratch ---------------------------------------------
__device__ __align__(16) float g_tbl[H3 * V];      // gi table [3H][V] (incl b_ih)
__device__ __align__(16) float g_h[2][H * B];      // hidden state [j][b], ping-pong
__device__ __align__(16) float g_qs[UD * B];       // softmax-weighted u: [d][b]
__device__ __align__(16) float g_ccT[H * B];       // concat-proj output [j][b]
__device__ __align__(16) float g_outWT[H * 64];    // out_W transposed+padded [j][64]
__device__ __align__(16) float g_catM[H * UD];     // cat_W[:,512:] @ mem_W  [j][d]
__device__ float g_catb2[H];                       // cat_b + cat_W[:,512:] @ mem_b
__device__ int g_tok[B];
__device__ unsigned g_cnt;                          // monotonic barrier counter

// ---------------- L1-bypassing ld/st (cross-CTA state) -----------------------
__device__ __forceinline__ float ldcg(const float* p) {
    float v; asm volatile("ld.global.cg.f32 %0, [%1];" : "=f"(v) : "l"(p)); return v;
}
__device__ __forceinline__ float4 ldcg4(const float4* p) {
    float4 v;
    asm volatile("ld.global.cg.v4.f32 {%0,%1,%2,%3}, [%4];"
                 : "=f"(v.x), "=f"(v.y), "=f"(v.z), "=f"(v.w) : "l"(p));
    return v;
}
__device__ __forceinline__ void stcg(float* p, float v) {
    asm volatile("st.global.cg.f32 [%0], %1;" :: "l"(p), "f"(v));
}
__device__ __forceinline__ int ldcg_i(const int* p) {
    int v; asm volatile("ld.global.cg.s32 %0, [%1];" : "=r"(v) : "l"(p)); return v;
}
__device__ __forceinline__ void stcg_i(int* p, int v) {
    asm volatile("st.global.cg.s32 [%0], %1;" :: "l"(p), "r"(v));
}

// ---------------- grid barrier: release/acquire, NO L1 flush -----------------
__device__ __forceinline__ void gbar(unsigned& target) {
    __syncthreads();
    if (threadIdx.x == 0) {
        target += NCTA;
        unsigned prev;
        asm volatile("atom.release.gpu.global.add.u32 %0, [%1], %2;"
                     : "=r"(prev) : "l"(&g_cnt), "r"(1u) : "memory");
        if (prev + 1u != target) {
            unsigned cur;
            do {
                asm volatile("ld.acquire.gpu.global.u32 %0, [%1];"
                             : "=r"(cur) : "l"(&g_cnt) : "memory");
            } while ((int)(cur - target) < 0);
        }
    }
    __syncthreads();
}

__device__ __forceinline__ float sigf(float x) { return 1.f / (1.f + expf(-x)); }

// ---------------- prep kernels -----------------------------------------------
__global__ void prep_tbl(const float* __restrict__ embed,
                         const float* __restrict__ W_ih,
                         const float* __restrict__ b_ih) {
    int jg = blockIdx.x;
    int v = threadIdx.x;
    if (v >= V) return;
    const float* wr = W_ih + (size_t)jg * H;
    const float* er = embed + (size_t)v * H;
    float acc = b_ih[jg];
#pragma unroll 4
    for (int k = 0; k < H; ++k) acc += er[k] * wr[k];
    g_tbl[jg * V + v] = acc;
}

__global__ void prep_h0(const float* __restrict__ latent,
                        const float* __restrict__ hid_W,
                        const float* __restrict__ hid_b) {
    int j = blockIdx.x;
    int b = threadIdx.x;
    const float* wr = hid_W + (size_t)j * LD;
    const float* lt = latent + (size_t)b * LD;
    float acc = hid_b[j];
#pragma unroll 4
    for (int k = 0; k < LD; ++k) acc += lt[k] * wr[k];
    g_h[0][j * B + b] = acc;
}

// catM[j][d] = sum_k cat_W[j][512+k] * mem_W[k][d];  catb2[j] folds mem_b in.
__global__ void prep_catM(const float* __restrict__ cat_W,
                          const float* __restrict__ mem_W,
                          const float* __restrict__ mem_b,
                          const float* __restrict__ cat_b) {
    int j = blockIdx.x;
    int d = threadIdx.x;
    const float* cw = cat_W + (size_t)j * (2 * H) + H;
    float acc = 0.f;
#pragma unroll 4
    for (int k = 0; k < H; ++k) acc += cw[k] * mem_W[k * UD + d];
    g_catM[j * UD + d] = acc;
    if (d == 0) {
        float s = cat_b[j];
        for (int k = 0; k < H; ++k) s += cw[k] * mem_b[k];
        g_catb2[j] = s;
    }
}

__global__ void prep_misc(const float* __restrict__ out_W) {
    if (blockIdx.x == 0 && threadIdx.x == 0) g_cnt = 0u;   // reset for graph replay
    int total = H * 64 + B;
    for (int idx = blockIdx.x * blockDim.x + threadIdx.x; idx < total;
         idx += gridDim.x * blockDim.x) {
        if (idx < H * 64) {
            int j = idx >> 6, v = idx & 63;
            g_outWT[idx] = (v < V) ? out_W[v * H + j] : 0.f;
        } else {
            g_tok[idx - H * 64] = 0;   // SOS
        }
    }
}

// ---------------- main persistent decoder ------------------------------------
__global__ void __launch_bounds__(NT, 1)
decoder_kernel(const float* __restrict__ u,        // [B,L,UD]
               const float* __restrict__ W_hh,     // [3H,H]
               const float* __restrict__ b_hh,     // [3H]
               const float* __restrict__ mem_W,    // [H,UD]
               const float* __restrict__ mem_b,    // [H]
               const float* __restrict__ cat_W,    // [H,2H]
               const float* __restrict__ out_b,    // [V]
               float* __restrict__ out)            // [B,V,L]
{
    extern __shared__ float DS[];
    float* sW    = DS;            // 12 x 512 : W_hh rows (r,z,n) for jl 0..3
    float* sCatH = DS + 6144;     // 4 x 512  : cat_W h-half rows
    float* sCatM = DS + 8192;     // 4 x 128  : catM rows
    float* SC    = DS + 8704;     // 8192 scratch
    const int tid = threadIdx.x;
    const int cta = blockIdx.x;
    const int jc  = cta * 4;

    // ---- one-time persistent weight load (survives all barriers) ----
    for (int i = tid; i < 6144; i += NT) {
        int r = i >> 9, k = i & 511;
        int g = r >> 2, jl0 = r & 3;
        sW[i] = W_hh[(size_t)(g * H + jc + jl0) * H + k];
    }
    for (int i = tid; i < 2048; i += NT)
        sCatH[i] = cat_W[(size_t)(jc + (i >> 9)) * (2 * H) + (i & 511)];
    for (int i = tid; i < 512; i += NT)
        sCatM[i] = g_catM[(jc + (i >> 7)) * UD + (i & 127)];

    const int jl = tid >> 7, bb = tid & 127;
    const int j = jc + jl;
    const float bhr = b_hh[j], bhz = b_hh[H + j], bhn = b_hh[2 * H + j];
    const float ccb = g_catb2[j];
    __syncthreads();

    unsigned bar_t = 0;

    for (int t = 0; t < L; ++t) {
        const float* hin = g_h[t & 1];
        float* hout = g_h[(t + 1) & 1];

        // ================= P1: GRU (thread = (jl, b), no k-reduction) ========
        {
            float ar = 0.f, az = 0.f, an = 0.f;
            const float* wr = sW + jl * 512;
            const float* wz = sW + (4 + jl) * 512;
            const float* wn = sW + (8 + jl) * 512;
            for (int k0 = 0; k0 < H; k0 += 64) {
                __syncthreads();
                const float4* src = (const float4*)(hin + k0 * B);
                float4* dst = (float4*)SC;
#pragma unroll
                for (int i = 0; i < 4; ++i) dst[tid + i * NT] = ldcg4(src + tid + i * NT);
                __syncthreads();
#pragma unroll
                for (int kk = 0; kk < 64; kk += 4) {
                    float4 w_r = *(const float4*)(wr + k0 + kk);
                    float4 w_z = *(const float4*)(wz + k0 + kk);
                    float4 w_n = *(const float4*)(wn + k0 + kk);
#pragma unroll
                    for (int q = 0; q < 4; ++q) {
                        float hv = SC[(kk + q) * B + bb];
                        ar += ((const float*)&w_r)[q] * hv;
                        az += ((const float*)&w_z)[q] * hv;
                        an += ((const float*)&w_n)[q] * hv;
                    }
                }
            }
            int tk = ldcg_i(&g_tok[bb]);
            float gr = g_tbl[j * V + tk];
            float gz = g_tbl[(H + j) * V + tk];
            float gn = g_tbl[(2 * H + j) * V + tk];
            float hv = ldcg(&hin[j * B + bb]);
            float r = sigf(gr + ar + bhr);
            float z = sigf(gz + az + bhz);
            float n = tanhf(gn + r * (an + bhn));
            stcg(&hout[j * B + bb], (1.f - z) * n + z * hv);
        }
        gbar(bar_t);

        // ================= P2: attention -> q_s (CTA = batch element) ========
        {
            const int b = cta;
            const float* hn = hout;
            SC[tid] = ldcg(&hn[tid * B + b]);           // stage h_new[.,b]
            __syncthreads();
            {   // p[d] partials over 4 j-groups
                int d = tid & 127, jg = tid >> 7;
                float acc = 0.f;
                const float* mw = mem_W + (size_t)(jg * 128) * UD + d;
                const float* hh = SC + jg * 128;
#pragma unroll 16
                for (int jj = 0; jj < 128; ++jj) acc += mw[jj * UD] * hh[jj];
                SC[512 + tid] = acc;
            }
            {   // sbias = h_new . mem_b
                float sp = SC[tid] * mem_b[tid];
#pragma unroll
                for (int o = 16; o > 0; o >>= 1) sp += __shfl_xor_sync(~0u, sp, o);
                if ((tid & 31) == 0) SC[1152 + (tid >> 5)] = sp;
            }
            __syncthreads();
            if (tid < 128)
                SC[1024 + tid] = SC[512 + tid] + SC[640 + tid] + SC[768 + tid] + SC[896 + tid];
            if (tid == 0) {
                float s = 0.f;
#pragma unroll
                for (int i = 0; i < 16; ++i) s += SC[1152 + i];
                SC[1168] = s;
            }
            __syncthreads();
            const float sbias = SC[1168];
            const int lane = tid & 31, w = tid >> 5;
            float4 pv = *(const float4*)(SC + 1024 + lane * 4);
            const float* ub = u + (size_t)b * (L * UD) + lane * 4;
            // two-stream online softmax over L with weighted-u accumulation
            float m0 = -1e30f, Z0 = 0.f, m1 = -1e30f, Z1 = 0.f;
            float4 q0 = {0, 0, 0, 0}, q1 = {0, 0, 0, 0};
            for (int l0 = w; l0 < L; l0 += 32) {
                int l1 = l0 + 16;
                bool has1 = (l1 < L);
                float4 u0 = *(const float4*)(ub + (size_t)l0 * UD);
                float4 u1 = has1 ? *(const float4*)(ub + (size_t)l1 * UD)
                                 : make_float4(0, 0, 0, 0);
                float s0v = u0.x * pv.x + u0.y * pv.y + u0.z * pv.z + u0.w * pv.w;
                float s1v = u1.x * pv.x + u1.y * pv.y + u1.z * pv.z + u1.w * pv.w;
#pragma unroll
                for (int o = 16; o > 0; o >>= 1) {
                    s0v += __shfl_xor_sync(~0u, s0v, o);
                    s1v += __shfl_xor_sync(~0u, s1v, o);
                }
                s0v += sbias; s1v += sbias;
                {
                    float mn = fmaxf(m0, s0v);
                    float sc = expf(m0 - mn), wt = expf(s0v - mn);
                    Z0 = Z0 * sc + wt;
                    q0.x = q0.x * sc + wt * u0.x; q0.y = q0.y * sc + wt * u0.y;
                    q0.z = q0.z * sc + wt * u0.z; q0.w = q0.w * sc + wt * u0.w;
                    m0 = mn;
                }
                if (has1) {
                    float mn = fmaxf(m1, s1v);
                    float sc = expf(m1 - mn), wt = expf(s1v - mn);
                    Z1 = Z1 * sc + wt;
                    q1.x = q1.x * sc + wt * u1.x; q1.y = q1.y * sc + wt * u1.y;
                    q1.z = q1.z * sc + wt * u1.z; q1.w = q1.w * sc + wt * u1.w;
                    m1 = mn;
                }
            }
            {
                float mn = fmaxf(m0, m1);
                float sc0 = expf(m0 - mn), sc1 = expf(m1 - mn);
                Z0 = Z0 * sc0 + Z1 * sc1;
                q0.x = q0.x * sc0 + q1.x * sc1; q0.y = q0.y * sc0 + q1.y * sc1;
                q0.z = q0.z * sc0 + q1.z * sc1; q0.w = q0.w * sc0 + q1.w * sc1;
                m0 = mn;
            }
            *(float4*)(SC + 1280 + w * 128 + lane * 4) = q0;
            if (lane == 0) { SC[3328 + w] = m0; SC[3344 + w] = Z0; }
            __syncthreads();
            if (tid == 0) {
                float M = SC[3328];
                for (int i = 1; i < 16; ++i) M = fmaxf(M, SC[3328 + i]);
                float Zt = 0.f;
                for (int i = 0; i < 16; ++i) {
                    float e = expf(SC[3328 + i] - M);
                    SC[3360 + i] = e;
                    Zt += e * SC[3344 + i];
                }
                SC[3376] = 1.f / Zt;
            }
            __syncthreads();
            if (tid < 128) {
                float acc = 0.f;
#pragma unroll
                for (int i = 0; i < 16; ++i) acc += SC[3360 + i] * SC[1280 + i * 128 + tid];
                stcg(&g_qs[tid * B + b], acc * SC[3376]);
            }
        }
        gbar(bar_t);

        // ================= P3: cc = tanh(catW_h@h + catM@q_s + b2) ===========
        {
            float acc = 0.f;
            const float* wc = sCatH + jl * 512;
            for (int k0 = 0; k0 < H; k0 += 64) {
                __syncthreads();
                const float4* src = (const float4*)(hout + k0 * B);
                float4* dst = (float4*)SC;
#pragma unroll
                for (int i = 0; i < 4; ++i) dst[tid + i * NT] = ldcg4(src + tid + i * NT);
                __syncthreads();
#pragma unroll
                for (int kk = 0; kk < 64; kk += 4) {
                    float4 w4 = *(const float4*)(wc + k0 + kk);
#pragma unroll
                    for (int q = 0; q < 4; ++q)
                        acc += ((const float*)&w4)[q] * SC[(kk + q) * B + bb];
                }
            }
            const float* wm = sCatM + jl * 128;
#pragma unroll 8
            for (int d = 0; d < UD; d += 4) {
                float4 w4 = *(const float4*)(wm + d);
                acc += w4.x * ldcg(&g_qs[d * B + bb]);
                acc += w4.y * ldcg(&g_qs[(d + 1) * B + bb]);
                acc += w4.z * ldcg(&g_qs[(d + 2) * B + bb]);
                acc += w4.w * ldcg(&g_qs[(d + 3) * B + bb]);
            }
            stcg(&g_ccT[j * B + bb], tanhf(acc + ccb));
        }
        gbar(bar_t);

        // ================= P4: logits + argmax (CTA = batch) =================
        {
            const int b = cta;
            const int v = tid & 63, jg = tid >> 6;
            float acc = 0.f;
            const float* op = g_outWT + jg * 64 * 64 + v;
            const float* cp = g_ccT + (size_t)(jg * 64) * B + b;
#pragma unroll 8
            for (int i = 0; i < 64; ++i) acc += op[i * 64] * ldcg(cp + i * B);
            SC[tid] = acc;
            __syncthreads();
            if (tid < V) {
                float s = 0.f;
#pragma unroll
                for (int g = 0; g < 8; ++g) s += SC[g * 64 + tid];
                float logit = s + out_b[tid];
                out[((size_t)b * V + tid) * L + t] = logit;
                SC[512 + tid] = logit;
            }
            __syncthreads();
            if (tid == 0) {   // first-occurrence argmax
                float best = SC[512];
                int bi = 0;
                for (int v2 = 1; v2 < V; ++v2) {
                    float lv = SC[512 + v2];
                    if (lv > best) { best = lv; bi = v2; }
                }
                stcg_i(&g_tok[b], bi);
            }
        }
        gbar(bar_t);
    }
}

// ---------------- launch -----------------------------------------------------
extern "C" void kernel_launch(void* const* d_in, const int* in_sizes, int n_in,
                              void* d_out, int out_size) {
    const float* latent = (const float*)d_in[0];
    const float* u      = (const float*)d_in[1];
    // d_in[2] = target (unused: eval/greedy mode)
    const float* embed  = (const float*)d_in[3];
    const float* hid_W  = (const float*)d_in[4];
    const float* hid_b  = (const float*)d_in[5];
    const float* mem_W  = (const float*)d_in[6];
    const float* mem_b  = (const float*)d_in[7];
    const float* W_ih   = (const float*)d_in[8];
    const float* W_hh   = (const float*)d_in[9];
    const float* b_ih   = (const float*)d_in[10];
    const float* b_hh   = (const float*)d_in[11];
    const float* cat_W  = (const float*)d_in[12];
    const float* cat_b  = (const float*)d_in[13];
    const float* out_W  = (const float*)d_in[14];
    const float* out_b  = (const float*)d_in[15];
    float* out = (float*)d_out;

    cudaFuncSetAttribute(decoder_kernel,
                         cudaFuncAttributeMaxDynamicSharedMemorySize, SMEM_BYTES);

    prep_tbl<<<H3, 64>>>(embed, W_ih, b_ih);
    prep_h0<<<H, B>>>(latent, hid_W, hid_b);
    prep_catM<<<H, UD>>>(cat_W, mem_W, mem_b, cat_b);
    prep_misc<<<64, 256>>>(out_W);
    decoder_kernel<<<NCTA, NT, SMEM_BYTES>>>(u, W_hh, b_hh, mem_W, mem_b,
                                             cat_W, out_b, out);
}

// round 3
// speedup vs baseline: 1.8207x; 1.0624x over previous
#include <cuda_runtime.h>
#include <math.h>
#include <stdint.h>

#define B   128
#define L   500
#define H   512
#define LD  256
#define UD  128
#define V   33
#define H3  1536
#define NCTA 128
#define NT   512

// dynamic smem float offsets
#define SO_W     0        // 12x512 W_hh
#define SO_CATH  6144     // 4x512 cat_W h-half
#define SO_CATM  8192     // 4x128 catM
#define SO_OUTW  8704     // 4x34  out_W rows for this CTA's j's
#define SO_CC    8840     // 4x128 cc values
#define SO_SB    9360     // 2x8192 staging / scratch
#define SMEM_FLOATS 25744
#define SMEM_BYTES  (SMEM_FLOATS * 4)

// ---------------- device scratch ---------------------------------------------
__device__ __align__(16) float g_tbl[H3 * V];        // gi table [3H][V]
__device__ __align__(16) float g_h[2][H * B];        // hidden state [j][b] ping-pong
__device__ __align__(16) float g_qs[UD * B];         // softmax-weighted u [d][b]
__device__ __align__(16) float g_plog[NCTA * V * B]; // partial logits [cta][v][b]
__device__ __align__(16) float g_catM[H * UD];       // cat_W[:,512:] @ mem_W
__device__ float g_catb2[H];
__device__ int g_tok[B];
__device__ unsigned g_flags[128];                    // [0]=H [32]=Q [64]=L [96]=TOK

// ---------------- helpers ----------------------------------------------------
__device__ __forceinline__ float ldcg(const float* p) {
    float v; asm volatile("ld.global.cg.f32 %0, [%1];" : "=f"(v) : "l"(p)); return v;
}
__device__ __forceinline__ float4 ldcg4(const float4* p) {
    float4 v;
    asm volatile("ld.global.cg.v4.f32 {%0,%1,%2,%3}, [%4];"
                 : "=f"(v.x), "=f"(v.y), "=f"(v.z), "=f"(v.w) : "l"(p));
    return v;
}
__device__ __forceinline__ void stcg(float* p, float v) {
    asm volatile("st.global.cg.f32 [%0], %1;" :: "l"(p), "f"(v));
}
__device__ __forceinline__ int ldcg_i(const int* p) {
    int v; asm volatile("ld.global.cg.s32 %0, [%1];" : "=r"(v) : "l"(p)); return v;
}
__device__ __forceinline__ void stcg_i(int* p, int v) {
    asm volatile("st.global.cg.s32 [%0], %1;" :: "l"(p), "r"(v));
}
__device__ __forceinline__ void arrive(unsigned* f) {
    unsigned p;
    asm volatile("atom.release.gpu.global.add.u32 %0, [%1], %2;"
                 : "=r"(p) : "l"(f), "r"(1u) : "memory");
}
__device__ __forceinline__ void waitflag(unsigned* f, unsigned target) {
    unsigned cur;
    do {
        asm volatile("ld.acquire.gpu.global.u32 %0, [%1];"
                     : "=r"(cur) : "l"(f) : "memory");
    } while ((int)(cur - target) < 0);
}
__device__ __forceinline__ void cpa16(uint32_t dst, const void* src) {
    asm volatile("cp.async.cg.shared.global [%0], [%1], 16;" :: "r"(dst), "l"(src));
}
__device__ __forceinline__ void cpa_commit() { asm volatile("cp.async.commit_group;"); }
__device__ __forceinline__ void cpa_wait1() { asm volatile("cp.async.wait_group 1;"); }
__device__ __forceinline__ void cpa_wait0() { asm volatile("cp.async.wait_group 0;"); }
__device__ __forceinline__ float sigf(float x) { return 1.f / (1.f + expf(-x)); }

// ---------------- prep kernels -----------------------------------------------
__global__ void prep_tbl(const float* __restrict__ embed,
                         const float* __restrict__ W_ih,
                         const float* __restrict__ b_ih) {
    int jg = blockIdx.x, v = threadIdx.x;
    if (v >= V) return;
    const float* wr = W_ih + (size_t)jg * H;
    const float* er = embed + (size_t)v * H;
    float acc = b_ih[jg];
#pragma unroll 4
    for (int k = 0; k < H; ++k) acc += er[k] * wr[k];
    g_tbl[jg * V + v] = acc;
}

__global__ void prep_h0(const float* __restrict__ latent,
                        const float* __restrict__ hid_W,
                        const float* __restrict__ hid_b) {
    int j = blockIdx.x, b = threadIdx.x;
    const float* wr = hid_W + (size_t)j * LD;
    const float* lt = latent + (size_t)b * LD;
    float acc = hid_b[j];
#pragma unroll 4
    for (int k = 0; k < LD; ++k) acc += lt[k] * wr[k];
    g_h[0][j * B + b] = acc;
}

__global__ void prep_catM(const float* __restrict__ cat_W,
                          const float* __restrict__ mem_W,
                          const float* __restrict__ mem_b,
                          const float* __restrict__ cat_b) {
    int j = blockIdx.x, d = threadIdx.x;
    const float* cw = cat_W + (size_t)j * (2 * H) + H;
    float acc = 0.f;
#pragma unroll 4
    for (int k = 0; k < H; ++k) acc += cw[k] * mem_W[k * UD + d];
    g_catM[j * UD + d] = acc;
    if (d == 0) {
        float s = cat_b[j];
        for (int k = 0; k < H; ++k) s += cw[k] * mem_b[k];
        g_catb2[j] = s;
    }
}

__global__ void prep_misc() {
    int i = blockIdx.x * blockDim.x + threadIdx.x;
    if (i < 128) g_flags[i] = (i == 96) ? (unsigned)NCTA : 0u;  // TOK pre-armed
    if (i < B) g_tok[i] = 0;                                     // SOS
}

// ---------------- main persistent decoder ------------------------------------
__global__ void __launch_bounds__(NT, 1)
decoder_kernel(const float* __restrict__ u,        // [B,L,UD]
               const float* __restrict__ W_hh,     // [3H,H]
               const float* __restrict__ b_hh,     // [3H]
               const float* __restrict__ mem_W,    // [H,UD]
               const float* __restrict__ mem_b,    // [H]
               const float* __restrict__ cat_W,    // [H,2H]
               const float* __restrict__ out_W,    // [V,H]
               const float* __restrict__ out_b,    // [V]
               float* __restrict__ out)            // [B,V,L]
{
    extern __shared__ float DS[];
    float* sW    = DS + SO_W;
    float* sCatH = DS + SO_CATH;
    float* sCatM = DS + SO_CATM;
    float* sOutW = DS + SO_OUTW;
    float* sCC   = DS + SO_CC;
    float* SB    = DS + SO_SB;           // 16384 floats: 2 staging buffers / scratch
    const uint32_t sbAddr = (uint32_t)__cvta_generic_to_shared(SB);

    unsigned* FH = &g_flags[0];
    unsigned* FQ = &g_flags[32];
    unsigned* FL = &g_flags[64];
    unsigned* FT = &g_flags[96];

    const int tid = threadIdx.x;
    const int cta = blockIdx.x;
    const int jc  = cta * 4;

    // ---- one-time persistent weight loads ----
    for (int i = tid; i < 6144; i += NT) {
        int r = i >> 9, k = i & 511;
        sW[i] = W_hh[(size_t)((r >> 2) * H + jc + (r & 3)) * H + k];
    }
    for (int i = tid; i < 2048; i += NT)
        sCatH[i] = cat_W[(size_t)(jc + (i >> 9)) * (2 * H) + (i & 511)];
    for (int i = tid; i < 512; i += NT)
        sCatM[i] = g_catM[(jc + (i >> 7)) * UD + (i & 127)];
    for (int i = tid; i < 4 * V; i += NT) {
        int jl_ = i / V, v_ = i % V;
        sOutW[jl_ * 34 + v_] = out_W[(size_t)v_ * H + jc + jl_];
    }

    const int jl = tid >> 7, bb = tid & 127;
    const int j = jc + jl;
    const float bhr = b_hh[j], bhz = b_hh[H + j], bhn = b_hh[2 * H + j];
    const float ccb = g_catb2[j];
    const float* wr = sW + jl * 512;
    const float* wz = sW + (4 + jl) * 512;
    const float* wn = sW + (8 + jl) * 512;
    const float* wc = sCatH + jl * 512;
    const float* wm = sCatM + jl * 128;
    __syncthreads();

    for (int t = 0; t < L; ++t) {
        const float* hin = g_h[t & 1];
        float* hout = g_h[(t + 1) & 1];

        // ========== PHASE 1: GRU GEMM (tok-wait hidden at the end) ==========
        {
            float ar = 0.f, az = 0.f, an = 0.f, hself = 0.f;
            // stage chunk 0
            {
                const float4* s = (const float4*)hin + tid;
                uint32_t d0 = sbAddr + tid * 16;
#pragma unroll
                for (int i = 0; i < 4; ++i) cpa16(d0 + i * 8192, s + i * 512);
                cpa_commit();
            }
#pragma unroll 1
            for (int c = 0; c < 8; ++c) {
                if (c + 1 < 8) {
                    const float4* s = (const float4*)(hin + (c + 1) * 8192) + tid;
                    uint32_t d0 = sbAddr + ((c + 1) & 1) * 32768 + tid * 16;
#pragma unroll
                    for (int i = 0; i < 4; ++i) cpa16(d0 + i * 8192, s + i * 512);
                    cpa_commit();
                    cpa_wait1();
                } else {
                    cpa_wait0();
                }
                __syncthreads();
                const float* hc = SB + (c & 1) * 8192;
                const int kb = c * 64;
#pragma unroll
                for (int kk = 0; kk < 64; kk += 4) {
                    float4 w_r = *(const float4*)(wr + kb + kk);
                    float4 w_z = *(const float4*)(wz + kb + kk);
                    float4 w_n = *(const float4*)(wn + kb + kk);
#pragma unroll
                    for (int q = 0; q < 4; ++q) {
                        float hv = hc[(kk + q) * B + bb];
                        ar += ((const float*)&w_r)[q] * hv;
                        az += ((const float*)&w_z)[q] * hv;
                        an += ((const float*)&w_n)[q] * hv;
                    }
                }
                if (c == (j >> 6)) hself = hc[(j & 63) * B + bb];
                __syncthreads();
            }
            // epilogue: wait for tok(t) (hidden: argmax finished ~7us ago)
            if (tid == 0) waitflag(FT, (unsigned)NCTA * (t + 1));
            __syncthreads();
            int tk = ldcg_i(&g_tok[bb]);
            float gr = g_tbl[j * V + tk];
            float gz = g_tbl[(H + j) * V + tk];
            float gn = g_tbl[(2 * H + j) * V + tk];
            float r = sigf(gr + ar + bhr);
            float z = sigf(gz + az + bhz);
            float n = tanhf(gn + r * (an + bhn));
            stcg(&hout[j * B + bb], (1.f - z) * n + z * hself);
            __syncthreads();
            if (tid == 0) arrive(FH);
        }

        // ========== PHASE 2: attention (own b) + cc GEMM (own j's) ==========
        {
            if (tid == 0) waitflag(FH, (unsigned)NCTA * (t + 1));
            __syncthreads();
            const int b = cta;
            // --- P2: stage h_new[:, b] ---
            SB[tid] = ldcg(&hout[tid * B + b]);
            __syncthreads();
            {   // p[d] partials over 4 j-groups
                int d = tid & 127, jg = tid >> 7;
                float acc = 0.f;
                const float* mw = mem_W + (size_t)(jg * 128) * UD + d;
                const float* hh = SB + jg * 128;
#pragma unroll 16
                for (int jj = 0; jj < 128; ++jj) acc += mw[jj * UD] * hh[jj];
                SB[512 + tid] = acc;
            }
            {   // sbias = h_new . mem_b
                float sp = SB[tid] * mem_b[tid];
#pragma unroll
                for (int o = 16; o > 0; o >>= 1) sp += __shfl_xor_sync(~0u, sp, o);
                if ((tid & 31) == 0) SB[1024 + (tid >> 5)] = sp;
            }
            __syncthreads();
            if (tid < 128)
                SB[1056 + tid] = SB[512 + tid] + SB[640 + tid] + SB[768 + tid] + SB[896 + tid];
            if (tid == 0) {
                float s = 0.f;
#pragma unroll
                for (int i = 0; i < 16; ++i) s += SB[1024 + i];
                SB[1040] = s;
            }
            __syncthreads();
            const float sbias = SB[1040];
            const int lane = tid & 31, w = tid >> 5;
            float4 pv = *(const float4*)(SB + 1056 + lane * 4);
            const float* ub = u + (size_t)b * (L * UD) + lane * 4;
            float m0 = -1e30f, Z0 = 0.f, m1 = -1e30f, Z1 = 0.f;
            float4 q0 = {0, 0, 0, 0}, q1 = {0, 0, 0, 0};
            for (int l0 = w; l0 < L; l0 += 32) {
                int l1 = l0 + 16;
                bool has1 = (l1 < L);
                float4 u0 = ldcg4((const float4*)(ub + (size_t)l0 * UD));
                float4 u1 = has1 ? ldcg4((const float4*)(ub + (size_t)l1 * UD))
                                 : make_float4(0, 0, 0, 0);
                float s0v = u0.x * pv.x + u0.y * pv.y + u0.z * pv.z + u0.w * pv.w;
                float s1v = u1.x * pv.x + u1.y * pv.y + u1.z * pv.z + u1.w * pv.w;
#pragma unroll
                for (int o = 16; o > 0; o >>= 1) {
                    s0v += __shfl_xor_sync(~0u, s0v, o);
                    s1v += __shfl_xor_sync(~0u, s1v, o);
                }
                s0v += sbias; s1v += sbias;
                {
                    float mn = fmaxf(m0, s0v);
                    float sc = expf(m0 - mn), wt = expf(s0v - mn);
                    Z0 = Z0 * sc + wt;
                    q0.x = q0.x * sc + wt * u0.x; q0.y = q0.y * sc + wt * u0.y;
                    q0.z = q0.z * sc + wt * u0.z; q0.w = q0.w * sc + wt * u0.w;
                    m0 = mn;
                }
                if (has1) {
                    float mn = fmaxf(m1, s1v);
                    float sc = expf(m1 - mn), wt = expf(s1v - mn);
                    Z1 = Z1 * sc + wt;
                    q1.x = q1.x * sc + wt * u1.x; q1.y = q1.y * sc + wt * u1.y;
                    q1.z = q1.z * sc + wt * u1.z; q1.w = q1.w * sc + wt * u1.w;
                    m1 = mn;
                }
            }
            {
                float mn = fmaxf(m0, m1);
                float sc0 = expf(m0 - mn), sc1 = expf(m1 - mn);
                Z0 = Z0 * sc0 + Z1 * sc1;
                q0.x = q0.x * sc0 + q1.x * sc1; q0.y = q0.y * sc0 + q1.y * sc1;
                q0.z = q0.z * sc0 + q1.z * sc1; q0.w = q0.w * sc0 + q1.w * sc1;
                m0 = mn;
            }
            *(float4*)(SB + 1216 + w * 128 + lane * 4) = q0;
            if (lane == 0) { SB[3264 + w] = m0; SB[3280 + w] = Z0; }
            __syncthreads();
            if (tid == 0) {
                float M = SB[3264];
                for (int i = 1; i < 16; ++i) M = fmaxf(M, SB[3264 + i]);
                float Zt = 0.f;
                for (int i = 0; i < 16; ++i) {
                    float e = expf(SB[3264 + i] - M);
                    SB[3296 + i] = e;
                    Zt += e * SB[3280 + i];
                }
                SB[3312] = 1.f / Zt;
            }
            __syncthreads();
            if (tid < 128) {
                float acc = 0.f;
#pragma unroll
                for (int i = 0; i < 16; ++i) acc += SB[3296 + i] * SB[1216 + i * 128 + tid];
                stcg(&g_qs[tid * B + b], acc * SB[3312]);
            }
            __syncthreads();
            if (tid == 0) arrive(FQ);

            // --- P3h: cch = catW_h @ h_new (hides the Q wait) ---
            float cch = 0.f;
            {
                const float4* s = (const float4*)hout + tid;
                uint32_t d0 = sbAddr + tid * 16;
#pragma unroll
                for (int i = 0; i < 4; ++i) cpa16(d0 + i * 8192, s + i * 512);
                cpa_commit();
            }
#pragma unroll 1
            for (int c = 0; c < 8; ++c) {
                if (c + 1 < 8) {
                    const float4* s = (const float4*)(hout + (c + 1) * 8192) + tid;
                    uint32_t d0 = sbAddr + ((c + 1) & 1) * 32768 + tid * 16;
#pragma unroll
                    for (int i = 0; i < 4; ++i) cpa16(d0 + i * 8192, s + i * 512);
                    cpa_commit();
                    cpa_wait1();
                } else {
                    cpa_wait0();
                }
                __syncthreads();
                const float* hc = SB + (c & 1) * 8192;
                const int kb = c * 64;
#pragma unroll
                for (int kk = 0; kk < 64; kk += 4) {
                    float4 w4 = *(const float4*)(wc + kb + kk);
#pragma unroll
                    for (int q = 0; q < 4; ++q)
                        cch += ((const float*)&w4)[q] * hc[(kk + q) * B + bb];
                }
                __syncthreads();
            }
            // --- wait qs from all CTAs, stage it, finish cc, partial logits ---
            if (tid == 0) waitflag(FQ, (unsigned)NCTA * (t + 1));
            __syncthreads();
            {
                const float4* s = (const float4*)g_qs + tid;
                uint32_t d0 = sbAddr + tid * 16;
#pragma unroll
                for (int i = 0; i < 8; ++i) cpa16(d0 + i * 8192, s + i * 512);
                cpa_commit();
                cpa_wait0();
            }
            __syncthreads();
            float accq = 0.f;
#pragma unroll
            for (int d = 0; d < UD; d += 4) {
                float4 w4 = *(const float4*)(wm + d);
                accq += w4.x * SB[d * B + bb];
                accq += w4.y * SB[(d + 1) * B + bb];
                accq += w4.z * SB[(d + 2) * B + bb];
                accq += w4.w * SB[(d + 3) * B + bb];
            }
            sCC[jl * 128 + bb] = tanhf(cch + accq + ccb);
            __syncthreads();
            {   // partial logits for all b over this CTA's 4 j's
                int vg = tid >> 7, b2 = tid & 127;
#pragma unroll
                for (int i = 0; i < 9; ++i) {
                    int v = vg + 4 * i;
                    if (v < V) {
                        float a = sOutW[v] * sCC[b2]
                                + sOutW[34 + v] * sCC[128 + b2]
                                + sOutW[68 + v] * sCC[256 + b2]
                                + sOutW[102 + v] * sCC[384 + b2];
                        stcg(&g_plog[((size_t)cta * V + v) * B + b2], a);
                    }
                }
            }
            __syncthreads();
            if (tid == 0) arrive(FL);
        }

        // ========== PHASE 3: reduce logits, argmax, emit token ==========
        {
            if (tid == 0) waitflag(FL, (unsigned)NCTA * (t + 1));
            __syncthreads();
            const int b = cta;
            int cg = tid >> 6, v = tid & 63;
            if (v < V) {
                float acc = 0.f;
#pragma unroll
                for (int i = 0; i < 16; ++i) {
                    int c = cg * 16 + i;
                    acc += ldcg(&g_plog[((size_t)c * V + v) * B + b]);
                }
                SB[cg * 64 + v] = acc;
            }
            __syncthreads();
            if (tid < V) {
                float lg = out_b[tid];
#pragma unroll
                for (int g = 0; g < 8; ++g) lg += SB[g * 64 + tid];
                out[((size_t)b * V + tid) * L + t] = lg;
                SB[512 + tid] = lg;
            }
            __syncthreads();
            if (tid == 0) {
                float best = SB[512];
                int bi = 0;
                for (int v2 = 1; v2 < V; ++v2) {
                    float lv = SB[512 + v2];
                    if (lv > best) { best = lv; bi = v2; }
                }
                stcg_i(&g_tok[b], bi);
            }
            __syncthreads();
            if (tid == 0) arrive(FT);
        }
    }
}

// ---------------- launch -----------------------------------------------------
extern "C" void kernel_launch(void* const* d_in, const int* in_sizes, int n_in,
                              void* d_out, int out_size) {
    const float* latent = (const float*)d_in[0];
    const float* u      = (const float*)d_in[1];
    // d_in[2] = target (unused: eval/greedy)
    const float* embed  = (const float*)d_in[3];
    const float* hid_W  = (const float*)d_in[4];
    const float* hid_b  = (const float*)d_in[5];
    const float* mem_W  = (const float*)d_in[6];
    const float* mem_b  = (const float*)d_in[7];
    const float* W_ih   = (const float*)d_in[8];
    const float* W_hh   = (const float*)d_in[9];
    const float* b_ih   = (const float*)d_in[10];
    const float* b_hh   = (const float*)d_in[11];
    const float* cat_W  = (const float*)d_in[12];
    const float* cat_b  = (const float*)d_in[13];
    const float* out_W  = (const float*)d_in[14];
    const float* out_b  = (const float*)d_in[15];
    float* out = (float*)d_out;

    cudaFuncSetAttribute(decoder_kernel,
                         cudaFuncAttributeMaxDynamicSharedMemorySize, SMEM_BYTES);

    prep_tbl<<<H3, 64>>>(embed, W_ih, b_ih);
    prep_h0<<<H, B>>>(latent, hid_W, hid_b);
    prep_catM<<<H, UD>>>(cat_W, mem_W, mem_b, cat_b);
    prep_misc<<<1, 256>>>();
    decoder_kernel<<<NCTA, NT, SMEM_BYTES>>>(u, W_hh, b_hh, mem_W, mem_b,
                                             cat_W, out_W, out_b, out);
}